// round 14
// baseline (speedup 1.0000x reference)
#include <cuda_runtime.h>
#include <cuda_fp16.h>
#include <cstdint>

// HexConv, persistent-CTA fp16 mma.sync (m16n8k16, f32 accum):
//   512 thr, 16 warps = 8 M-groups x 2 N-halves (wm = wid>>1, wn = wid&1 -> SMSP
//   frag-load 6,6,5,5 balanced). Frags f = wm + 8u (u<2, f<11) -> 32 acc/thread
//   (hard rule from R9/R12/R13: 48 acc => 128 regs + spills).
//   Double-buffered fp16 grid; convert(b+1) issued before compute(b); ONE barrier
//   per batch. W fp16 in SMEM (shared). Traffic = 1512 LDS.128/batch (0.9x R10).
// K-permutation: per 32-k superblock, thread lc owns orig d = 8lc..8lc+7 -> all
// operand traffic is LDS.128; CELLB/WROWB == 64 mod 128 -> conflict-free phases.

#define NHEX   165
#define HD     64
#define OUTD   64
#define NCHUNK 7
#define CELLB  192
#define WROWB  960
#define NB     2048
#define THREADS 512
#define GRIDX  152

#define G_BYTES (221 * CELLB)                 // 42432 per buffer
#define W_BYTES (OUTD * WROWB)                // 61440
#define SMEM_BYTES (2 * G_BYTES + W_BYTES)    // 146304

__constant__ int OFFC[7] = {-17 * CELLB, -16 * CELLB, -1 * CELLB, 0,
                            1 * CELLB, 17 * CELLB, 18 * CELLB};

static __device__ __forceinline__ uint32_t pk(float a, float b) {
    __half2 h = __floats2half2_rn(a, b);
    return *(uint32_t*)&h;
}
static __device__ __forceinline__ void mma16816(float* c,
                                                uint32_t a0, uint32_t a1, uint32_t a2, uint32_t a3,
                                                uint32_t b0, uint32_t b1) {
    asm volatile(
        "mma.sync.aligned.m16n8k16.row.col.f32.f16.f16.f32 "
        "{%0,%1,%2,%3}, {%4,%5,%6,%7}, {%8,%9}, {%0,%1,%2,%3};"
        : "+f"(c[0]), "+f"(c[1]), "+f"(c[2]), "+f"(c[3])
        : "r"(a0), "r"(a1), "r"(a2), "r"(a3), "r"(b0), "r"(b1));
}

__global__ void __launch_bounds__(THREADS, 1)
hexconv_mma(const float* __restrict__ x, const float* __restrict__ W,
            const float* __restrict__ bias, float* __restrict__ out)
{
    extern __shared__ char smem[];
    char* G0 = smem;
    char* G1 = smem + G_BYTES;
    char* Wc = smem + 2 * G_BYTES;
    const int tid = threadIdx.x;

    // ---- one-time: zero both grid buffers (pad cells stay zero forever) ----
    for (int i = tid; i < 2 * G_BYTES / 16; i += THREADS)
        ((uint4*)smem)[i] = make_uint4(0, 0, 0, 0);

    // ---- one-time: stage W as fp16 ----
    const float4* Wg4 = (const float4*)W;
    for (int i = tid; i < OUTD * 112; i += THREADS) {
        int o = i / 112, k4 = i - o * 112;
        float4 v = Wg4[i];
        *(uint2*)(Wc + o * WROWB + k4 * 8) = make_uint2(pk(v.x, v.y), pk(v.z, v.w));
    }

    // ---- warp geometry: 16 warps = 8 M-groups x 2 N-halves ----
    const int wid = tid >> 5, lane = tid & 31;
    const int wm = wid >> 1;       // 0..7 ; frags f = wm + 8u
    const int wn = wid & 1;        // N half (32 cols)
    const int lr = lane >> 2, lc = lane & 3;
    const bool has2 = (wm < 3);    // u=1 frag valid (f = wm+8 < 11)

    float2 bv[4];
#pragma unroll
    for (int nf = 0; nf < 4; nf++)
        bv[nf] = ((const float2*)bias)[(wn * 32 + nf * 8 + 2 * lc) >> 1];

    // fragment row bases (clamped): rows n = (wm+8u)*16 + h*8 + lr
    int base[2][2], baseAdj[2][2];
#pragma unroll
    for (int u = 0; u < 2; u++) {
#pragma unroll
        for (int h = 0; h < 2; h++) {
            int n = (wm + 8 * u) * 16 + h * 8 + lr;
            if (n > 164) n = 164;
            int hr = n / 15, hc = n - 15 * hr;
            int bb = ((hr + 1) * 17 + (hc + 1)) * CELLB + 16 * lc;
            base[u][h]    = bb;
            baseAdj[u][h] = bb - (((hr + 1) & 1) ? CELLB : 0);
        }
    }

    // ---- staging map: 1320 uint4 groups; thread owns g = tid + 512j, j<3 ----
    int gdst[3];
#pragma unroll
    for (int j = 0; j < 3; j++) {
        int g = tid + THREADS * j;
        if (g < NHEX * 8) {
            int n = g >> 3, d8 = g & 7;
            int hr = n / 15, hc = n - 15 * hr;
            gdst[j] = ((hr + 1) * 17 + (hc + 1)) * CELLB + d8 * 16;
        } else gdst[j] = -1;
    }

    __syncthreads();   // zero + W staging complete

    // ---- convert first batch into buffer 0 ----
    {
        const float4* xs = (const float4*)(x + (size_t)blockIdx.x * (NHEX * HD));
#pragma unroll
        for (int j = 0; j < 3; j++)
            if (gdst[j] >= 0) {
                int g = tid + THREADS * j;
                float4 v0 = xs[2 * g], v1 = xs[2 * g + 1];
                *(uint4*)(G0 + gdst[j]) = make_uint4(pk(v0.x, v0.y), pk(v0.z, v0.w),
                                                     pk(v1.x, v1.y), pk(v1.z, v1.w));
            }
    }
    __syncthreads();   // buffer 0 ready

    int ib = 0;
    for (int b = blockIdx.x; b < NB; b += GRIDX) {
        char* cur = (ib == 0) ? G0 : G1;
        char* nxt = (ib == 0) ? G1 : G0;

        // ---- convert next batch into idle buffer (overlaps compute; no barrier) ----
        const int bn = b + GRIDX;
        if (bn < NB) {
            const float4* xs = (const float4*)(x + (size_t)bn * (NHEX * HD));
#pragma unroll
            for (int j = 0; j < 3; j++)
                if (gdst[j] >= 0) {
                    int g = tid + THREADS * j;
                    float4 v0 = xs[2 * g], v1 = xs[2 * g + 1];
                    *(uint4*)(nxt + gdst[j]) = make_uint4(pk(v0.x, v0.y), pk(v0.z, v0.w),
                                                          pk(v1.x, v1.y), pk(v1.z, v1.w));
                }
        }

        float acc[2][4][4];
#pragma unroll
        for (int u = 0; u < 2; u++)
#pragma unroll
            for (int nf = 0; nf < 4; nf++)
#pragma unroll
                for (int i = 0; i < 4; i++) acc[u][nf][i] = 0.f;

        const char* Wp0 = Wc + (wn * 32 + lr) * WROWB + 16 * lc;

#pragma unroll 1
        for (int c = 0; c < NCHUNK; c++) {
            const int off  = OFFC[c];
            const bool adj = (c < 2 || c > 4);
            const char* wp = Wp0 + c * 128;
#pragma unroll
            for (int sub = 0; sub < 2; sub++) {
                uint4 w[4];
#pragma unroll
                for (int nf = 0; nf < 4; nf++)
                    w[nf] = *(const uint4*)(wp + nf * (8 * WROWB) + sub * 64);
#pragma unroll
                for (int u = 0; u < 2; u++) {
                    if (u == 0 || has2) {
                        const int p0 = (adj ? baseAdj[u][0] : base[u][0]) + off + sub * 64;
                        const int p1 = (adj ? baseAdj[u][1] : base[u][1]) + off + sub * 64;
                        uint4 a0 = *(const uint4*)(cur + p0);
                        uint4 a1 = *(const uint4*)(cur + p1);
#pragma unroll
                        for (int nf = 0; nf < 4; nf++) {
                            mma16816(acc[u][nf], a0.x, a1.x, a0.y, a1.y, w[nf].x, w[nf].y);
                            mma16816(acc[u][nf], a0.z, a1.z, a0.w, a1.w, w[nf].z, w[nf].w);
                        }
                    }
                }
            }
        }

        // ---- epilogue: bias + masked stores ----
        float* ob = out + (size_t)b * (NHEX * OUTD);
#pragma unroll
        for (int u = 0; u < 2; u++) {
            if (u == 0 || has2) {
                const int f = wm + 8 * u;
                const int n1 = f * 16 + lr, n2 = n1 + 8;
#pragma unroll
                for (int nf = 0; nf < 4; nf++) {
                    const int cc = wn * 32 + nf * 8 + 2 * lc;
                    if (n1 < NHEX) {
                        float2 v = make_float2(acc[u][nf][0] + bv[nf].x,
                                               acc[u][nf][1] + bv[nf].y);
                        *(float2*)(ob + n1 * OUTD + cc) = v;
                    }
                    if (n2 < NHEX) {
                        float2 v = make_float2(acc[u][nf][2] + bv[nf].x,
                                               acc[u][nf][3] + bv[nf].y);
                        *(float2*)(ob + n2 * OUTD + cc) = v;
                    }
                }
            }
        }

        __syncthreads();   // publish next buffer; retire current
        ib ^= 1;
    }
}

extern "C" void kernel_launch(void* const* d_in, const int* in_sizes, int n_in,
                              void* d_out, int out_size)
{
    const float* x    = (const float*)d_in[0];
    const float* W    = (const float*)d_in[1];
    const float* bias = (const float*)d_in[2];
    float* out = (float*)d_out;

    cudaFuncSetAttribute(hexconv_mma,
                         cudaFuncAttributeMaxDynamicSharedMemorySize,
                         (int)SMEM_BYTES);
    hexconv_mma<<<GRIDX, THREADS, SMEM_BYTES>>>(x, W, bias, out);
}